// round 16
// baseline (speedup 1.0000x reference)
#include <cuda_runtime.h>
#include <cuda_fp16.h>
#include <math.h>

#define NT 2048
#define NH 2048
#define NI 1408
#define NE 8
#define TK 2
#define NP (NT*TK)

#define BM 128
// gemm1: BK=64, A [m][k/2] stride 36 (32 data + 4 pad; %32==4 -> conflict-free)
#define BK1 64
#define AR1 36
#define BR1 72    // B [k/2][64n] + 8 pad (%32==8 -> conflict-free)
// gemm2: BK=32 (R13/R15 proven config)
#define BK2 32
#define AR2 20
#define BR2 72

#define A1_WORDS (2 * BM * AR1)     // 9216
#define B1_WORDS (2 * 32 * BR1)     // 4608 per matrix
#define A2_WORDS (2 * BM * AR2)
#define B2_WORDS (2 * 16 * BR2)

// ---------------- scratch ----------------
__device__ int      g_cnt[NE];
__device__ int      g_off[NE + 1];
__device__ int      g_tok[NP];
__device__ float    g_wt[NP];
__device__ unsigned g_hidh[(size_t)NT * NH / 2];   // fp16x2 hidden
__device__ unsigned g_acth[(size_t)NP * NI / 2];   // fp16x2 activations

// ---------------- fused routing ----------------
__global__ __launch_bounds__(1024) void k_route(
    const int* __restrict__ idx, const float* __restrict__ w)
{
    __shared__ int scnt[NE], soff[NE], sfill[NE];
    int tid = threadIdx.x;
    if (tid < NE) { scnt[tid] = 0; sfill[tid] = 0; }
    __syncthreads();
    int my_e[4];
#pragma unroll
    for (int j = 0; j < 4; j++) {
        int i = tid + j * 1024;
        my_e[j] = idx[i];
        atomicAdd(&scnt[my_e[j]], 1);
    }
    __syncthreads();
    if (tid == 0) {
        int s = 0;
        for (int e = 0; e < NE; e++) {
            soff[e] = s; g_off[e] = s; g_cnt[e] = scnt[e]; s += scnt[e];
        }
        g_off[NE] = s;
    }
    __syncthreads();
#pragma unroll
    for (int j = 0; j < 4; j++) {
        int i = tid + j * 1024;
        int e = my_e[j];
        int pos = soff[e] + atomicAdd(&sfill[e], 1);
        g_tok[pos] = i / TK;
        g_wt[pos]  = w[i];
    }
}

// ---------------- fp16 helpers ----------------
__device__ __forceinline__ unsigned hpack(float lo, float hi) {
    __half2 h = __floats2half2_rn(lo, hi);
    return *(unsigned*)&h;
}
__device__ __forceinline__ uint4 hpack_rows(float4 r0, float4 r1) {
    uint4 w;
    w.x = hpack(r0.x, r1.x); w.y = hpack(r0.y, r1.y);
    w.z = hpack(r0.z, r1.z); w.w = hpack(r0.w, r1.w);
    return w;
}
__device__ __forceinline__ uint4 hpack_k(float4 a, float4 b) {
    uint4 w;
    w.x = hpack(a.x, a.y); w.y = hpack(a.z, a.w);
    w.z = hpack(b.x, b.y); w.w = hpack(b.z, b.w);
    return w;
}
__device__ __forceinline__ void mma16(float* c, const unsigned* a, const unsigned* b) {
    asm volatile(
        "mma.sync.aligned.m16n8k16.row.col.f32.f16.f16.f32 "
        "{%0,%1,%2,%3},{%4,%5,%6,%7},{%8,%9},{%0,%1,%2,%3};"
        : "+f"(c[0]), "+f"(c[1]), "+f"(c[2]), "+f"(c[3])
        : "r"(a[0]), "r"(a[1]), "r"(a[2]), "r"(a[3]), "r"(b[0]), "r"(b[1]));
}

// pre-round hidden to fp16 + zero output
__global__ void k_prep(const float* __restrict__ hidden, float* __restrict__ out) {
    int i = blockIdx.x * blockDim.x + threadIdx.x;
    float4 a = ((const float4*)hidden)[2 * i];
    float4 b = ((const float4*)hidden)[2 * i + 1];
    ((uint4*)g_hidh)[i] = hpack_k(a, b);
    ((float4*)out)[2 * i]     = make_float4(0.f, 0.f, 0.f, 0.f);
    ((float4*)out)[2 * i + 1] = make_float4(0.f, 0.f, 0.f, 0.f);
}

// ---------------- GEMM1: act = silu(X Wg) * (X Wu) ----------------
// CTA 128M x 64N x 2mat, BK=64, 4 warps (2M x 2N), warp tile 64M x 32N x 2mat.
__global__ __launch_bounds__(128, 2) void k_gemm1(
    const float* __restrict__ gate_w,
    const float* __restrict__ up_w)
{
    extern __shared__ unsigned sm[];
    unsigned* sA  = sm;                 // [2][128][AR1]
    unsigned* sBg = sA + A1_WORDS;      // [2][32][BR1]
    unsigned* sBu = sBg + B1_WORDS;
    int* toks = (int*)(sBu + B1_WORDS);

    int e = blockIdx.x % NE, cnt = g_cnt[e];
    int m0 = blockIdx.z * BM;
    if (m0 >= cnt) return;
    int base = g_off[e];
    int n0 = blockIdx.y * 64;
    int tid = threadIdx.x;

    if (tid < BM) {
        int m = m0 + tid;
        toks[tid] = (m < cnt) ? g_tok[base + m] : g_tok[base];
    }
    __syncthreads();

    const float* gp = gate_w + (size_t)e * NH * NI;
    const float* up = up_w   + (size_t)e * NH * NI;

    // A: 1 thread per row, 8 uint4 fp16 copy per K-tile (64 k = 32 words)
    const unsigned* aSrc = g_hidh + (size_t)toks[tid] * (NH / 2);
    unsigned* aDst0 = sA + tid * AR1;

    // B: 4 slots per matrix; slot s: idx = tid + 128s -> k2 = idx>>4 (0..31), n4 = (idx&15)*4
    int k2s[4], n4s[4];
    unsigned bOffs[4];
    const float *gS[4], *uS[4];
#pragma unroll
    for (int s2 = 0; s2 < 4; s2++) {
        int idx = tid + 128 * s2;
        k2s[s2] = idx >> 4;
        n4s[s2] = (idx & 15) << 2;
        bOffs[s2] = k2s[s2] * BR1 + n4s[s2];
        gS[s2] = gp + (size_t)(2 * k2s[s2]) * NI + n0 + n4s[s2];
        uS[s2] = up + (size_t)(2 * k2s[s2]) * NI + n0 + n4s[s2];
    }

    // prologue: stage 0
    {
#pragma unroll
        for (int j = 0; j < 8; j++)
            *(uint4*)(aDst0 + 4 * j) = ((const uint4*)aSrc)[j];
#pragma unroll
        for (int s2 = 0; s2 < 4; s2++) {
            *(uint4*)(sBg + bOffs[s2]) = hpack_rows(*(const float4*)gS[s2], *(const float4*)(gS[s2] + NI));
            *(uint4*)(sBu + bOffs[s2]) = hpack_rows(*(const float4*)uS[s2], *(const float4*)(uS[s2] + NI));
        }
    }
    __syncthreads();

    int lane = tid & 31, wid = tid >> 5;
    int wm = (wid & 1) * 64, wn = (wid >> 1) * 32;
    int grp = lane >> 2, tig = lane & 3;

    float accg[4][4][4] = {}, accu[4][4][4] = {};
    uint4 pa[8];
    float4 pg[8], pu[8];

    for (int k0 = 0; k0 < NH; k0 += BK1) {
        int s = (k0 / BK1) & 1;
        bool nxt = (k0 + BK1) < NH;
        if (nxt) {
            int kn = k0 + BK1;
            const unsigned* as = aSrc + (kn >> 1);
#pragma unroll
            for (int j = 0; j < 8; j++) pa[j] = ((const uint4*)as)[j];
#pragma unroll
            for (int s2 = 0; s2 < 4; s2++) {
                pg[2*s2]     = *(const float4*)(gS[s2] + (size_t)kn * NI);
                pg[2*s2 + 1] = *(const float4*)(gS[s2] + (size_t)(kn + 1) * NI);
                pu[2*s2]     = *(const float4*)(uS[s2] + (size_t)kn * NI);
                pu[2*s2 + 1] = *(const float4*)(uS[s2] + (size_t)(kn + 1) * NI);
            }
        }

        const unsigned* As = sA  + s * BM * AR1;
        const unsigned* Bg = sBg + s * 32 * BR1;
        const unsigned* Bu = sBu + s * 32 * BR1;

#pragma unroll
        for (int kk = 0; kk < 4; kk++) {
            int k8 = kk * 8;
            unsigned a[4][4];
#pragma unroll
            for (int mi = 0; mi < 4; mi++) {
                int mb = wm + mi * 16 + grp;
                a[mi][0] = As[(mb    ) * AR1 + k8 + tig    ];
                a[mi][1] = As[(mb + 8) * AR1 + k8 + tig    ];
                a[mi][2] = As[(mb    ) * AR1 + k8 + tig + 4];
                a[mi][3] = As[(mb + 8) * AR1 + k8 + tig + 4];
            }
#pragma unroll
            for (int nj = 0; nj < 4; nj++) {
                int nb = wn + nj * 8 + grp;
                unsigned b[2];
                b[0] = Bg[(k8 + tig    ) * BR1 + nb];
                b[1] = Bg[(k8 + tig + 4) * BR1 + nb];
#pragma unroll
                for (int mi = 0; mi < 4; mi++) mma16(accg[mi][nj], a[mi], b);
                b[0] = Bu[(k8 + tig    ) * BR1 + nb];
                b[1] = Bu[(k8 + tig + 4) * BR1 + nb];
#pragma unroll
                for (int mi = 0; mi < 4; mi++) mma16(accu[mi][nj], a[mi], b);
            }
        }

        if (nxt) {
            int sn = s ^ 1;
            unsigned* An  = sA  + sn * BM * AR1 + tid * AR1;
            unsigned* Bgn = sBg + sn * 32 * BR1;
            unsigned* Bun = sBu + sn * 32 * BR1;
#pragma unroll
            for (int j = 0; j < 8; j++) *(uint4*)(An + 4 * j) = pa[j];
#pragma unroll
            for (int s2 = 0; s2 < 4; s2++) {
                *(uint4*)(Bgn + bOffs[s2]) = hpack_rows(pg[2*s2], pg[2*s2 + 1]);
                *(uint4*)(Bun + bOffs[s2]) = hpack_rows(pu[2*s2], pu[2*s2 + 1]);
            }
        }
        __syncthreads();
    }

    // epilogue: silu(g)*u -> g_acth
#pragma unroll
    for (int mi = 0; mi < 4; mi++) {
#pragma unroll
        for (int nj = 0; nj < 4; nj++) {
            int mrow = wm + mi * 16 + grp;
            int ncol = n0 + wn + nj * 8 + tig * 2;
#pragma unroll
            for (int h = 0; h < 2; h++) {
                int mr = m0 + mrow + h * 8;
                if (mr < cnt) {
                    float g0 = accg[mi][nj][2*h],     u0 = accu[mi][nj][2*h];
                    float g1 = accg[mi][nj][2*h + 1], u1 = accu[mi][nj][2*h + 1];
                    float v0 = (g0 / (1.f + __expf(-g0))) * u0;
                    float v1 = (g1 / (1.f + __expf(-g1))) * u1;
                    g_acth[(size_t)(base + mr) * (NI / 2) + (ncol >> 1)] = hpack(v0, v1);
                }
            }
        }
    }
}

// ---------------- GEMM2: out[token] += wt * (act . Wd), dual-N ----------------
// R13/R15 config: 256 threads, 8 warps (4M x 2N), warp 32x32 x dual-N matrices.
__global__ __launch_bounds__(256, 2) void k_gemm2(
    const float* __restrict__ down_w,
    float* __restrict__ out)
{
    extern __shared__ unsigned sm[];
    unsigned* sA  = sm;
    unsigned* sB0 = sA + A2_WORDS;
    unsigned* sB1 = sB0 + B2_WORDS;
    int*   toks = (int*)(sB1 + B2_WORDS);
    float* wts  = (float*)(toks + BM);

    int e = blockIdx.z, cnt = g_cnt[e];
    int m0 = blockIdx.x * BM;
    if (m0 >= cnt) return;
    int base = g_off[e];
    int n0 = blockIdx.y * 128;
    int tid = threadIdx.x;

    if (tid < BM) {
        int m = m0 + tid;
        toks[tid] = (m < cnt) ? g_tok[base + m] : 0;
        wts[tid]  = (m < cnt) ? g_wt[base + m] : 0.f;
    }
    __syncthreads();

    const float* dp = down_w + (size_t)e * NI * NH;

    int a_m = tid >> 1, a_w = (tid & 1) << 3;
    int am = m0 + a_m;
    const unsigned* aSrc = g_acth + (size_t)(base + (am < cnt ? am : m0)) * (NI / 2) + a_w;
    unsigned* aDstBase = sA + a_m * AR2 + a_w;
    int b_k2 = tid >> 4, b_n4 = (tid & 15) << 2;
    const float* bSrc0 = dp + (size_t)(2 * b_k2) * NH + n0 + b_n4;
    const float* bSrc1 = bSrc0 + 64;
    unsigned bOff = b_k2 * BR2 + b_n4;

    {
        *(uint4*)(aDstBase)     = *(const uint4*)(aSrc);
        *(uint4*)(aDstBase + 4) = *(const uint4*)(aSrc + 4);
        float4 v00 = *(const float4*)(bSrc0);
        float4 v01 = *(const float4*)(bSrc0 + NH);
        float4 v10 = *(const float4*)(bSrc1);
        float4 v11 = *(const float4*)(bSrc1 + NH);
        *(uint4*)(sB0 + bOff) = hpack_rows(v00, v01);
        *(uint4*)(sB1 + bOff) = hpack_rows(v10, v11);
    }
    __syncthreads();

    int lane = tid & 31, wid = tid >> 5;
    int wm = (wid & 3) * 32, wn = (wid >> 2) * 32;
    int grp = lane >> 2, tig = lane & 3;

    float acc0[2][4][4] = {}, acc1[2][4][4] = {};
    uint4 pa[2];
    float4 pb0[2], pb1[2];

    for (int k0 = 0; k0 < NI; k0 += BK2) {
        int s = (k0 / BK2) & 1;
        bool nxt = (k0 + BK2) < NI;
        if (nxt) {
            int kn = k0 + BK2;
            pa[0] = *(const uint4*)(aSrc + (kn >> 1));
            pa[1] = *(const uint4*)(aSrc + (kn >> 1) + 4);
            pb0[0] = *(const float4*)(bSrc0 + (size_t)kn * NH);
            pb0[1] = *(const float4*)(bSrc0 + (size_t)(kn + 1) * NH);
            pb1[0] = *(const float4*)(bSrc1 + (size_t)kn * NH);
            pb1[1] = *(const float4*)(bSrc1 + (size_t)(kn + 1) * NH);
        }

        const unsigned* As = sA  + s * BM * AR2;
        const unsigned* B0 = sB0 + s * 16 * BR2;
        const unsigned* B1 = sB1 + s * 16 * BR2;

#pragma unroll
        for (int kk = 0; kk < 2; kk++) {
            int k8 = kk * 8;
            unsigned a[2][4];
#pragma unroll
            for (int mi = 0; mi < 2; mi++) {
                int mb = wm + mi * 16 + grp;
                a[mi][0] = As[(mb    ) * AR2 + k8 + tig    ];
                a[mi][1] = As[(mb + 8) * AR2 + k8 + tig    ];
                a[mi][2] = As[(mb    ) * AR2 + k8 + tig + 4];
                a[mi][3] = As[(mb + 8) * AR2 + k8 + tig + 4];
            }
#pragma unroll
            for (int nj = 0; nj < 4; nj++) {
                int nb = wn + nj * 8 + grp;
                unsigned b[2];
                b[0] = B0[(k8 + tig    ) * BR2 + nb];
                b[1] = B0[(k8 + tig + 4) * BR2 + nb];
                mma16(acc0[0][nj], a[0], b);
                mma16(acc0[1][nj], a[1], b);
                b[0] = B1[(k8 + tig    ) * BR2 + nb];
                b[1] = B1[(k8 + tig + 4) * BR2 + nb];
                mma16(acc1[0][nj], a[0], b);
                mma16(acc1[1][nj], a[1], b);
            }
        }

        if (nxt) {
            int sn = s ^ 1;
            unsigned* An  = sA  + sn * BM * AR2 + a_m * AR2 + a_w;
            unsigned* Bn0 = sB0 + sn * 16 * BR2;
            unsigned* Bn1 = sB1 + sn * 16 * BR2;
            *(uint4*)(An)     = pa[0];
            *(uint4*)(An + 4) = pa[1];
            *(uint4*)(Bn0 + bOff) = hpack_rows(pb0[0], pb0[1]);
            *(uint4*)(Bn1 + bOff) = hpack_rows(pb1[0], pb1[1]);
        }
        __syncthreads();
    }

#pragma unroll
    for (int mi = 0; mi < 2; mi++) {
#pragma unroll
        for (int nj = 0; nj < 4; nj++) {
            int mloc = wm + mi * 16 + grp;
            int ncol = n0 + wn + nj * 8 + tig * 2;
#pragma unroll
            for (int h = 0; h < 2; h++) {
                int ml = mloc + h * 8;
                int mr = m0 + ml;
                if (mr < cnt) {
                    int   t = toks[ml];
                    float w = wts[ml];
                    float* dst = out + (size_t)t * NH + ncol;
                    asm volatile("red.global.add.v2.f32 [%0], {%1,%2};"
                                 :: "l"(dst), "f"(w * acc0[mi][nj][2*h]),
                                    "f"(w * acc0[mi][nj][2*h + 1]) : "memory");
                    asm volatile("red.global.add.v2.f32 [%0], {%1,%2};"
                                 :: "l"(dst + 64), "f"(w * acc1[mi][nj][2*h]),
                                    "f"(w * acc1[mi][nj][2*h + 1]) : "memory");
                }
            }
        }
    }
}

// ---------------- launch ----------------
extern "C" void kernel_launch(void* const* d_in, const int* in_sizes, int n_in,
                              void* d_out, int out_size)
{
    const float* hidden = (const float*)d_in[0];
    const int*   idx    = (const int*)  d_in[1];
    const float* topw   = (const float*)d_in[2];
    const float* gate_w = (const float*)d_in[3];
    const float* up_w   = (const float*)d_in[4];
    const float* down_w = (const float*)d_in[5];
    float* out = (float*)d_out;

    int smem1 = (A1_WORDS + 2 * B1_WORDS) * 4 + BM * 4;
    int smem2 = (A2_WORDS + 2 * B2_WORDS) * 4 + BM * 8;
    static int configured = 0;
    if (!configured) {
        cudaFuncSetAttribute(k_gemm1, cudaFuncAttributeMaxDynamicSharedMemorySize, smem1);
        cudaFuncSetAttribute(k_gemm2, cudaFuncAttributeMaxDynamicSharedMemorySize, smem2);
        configured = 1;
    }

    k_route<<<1, 1024>>>(idx, topw);
    k_prep<<<(NT * NH / 8) / 256, 256>>>(hidden, out);

    dim3 g1(NE, NI / 64, NP / BM);
    k_gemm1<<<g1, 128, smem1>>>(gate_w, up_w);

    dim3 g2(NP / BM, NH / 128, NE);
    k_gemm2<<<g2, 256, smem2>>>(down_w, out);
}

// round 17
// speedup vs baseline: 1.7388x; 1.7388x over previous
#include <cuda_runtime.h>
#include <cuda_fp16.h>
#include <math.h>

#define NT 2048
#define NH 2048
#define NI 1408
#define NE 8
#define TK 2
#define NP (NT*TK)

#define BM 128
#define BK 32
#define AR 20     // A [m][k/2] words + pad
#define BR1 72    // gemm1 B [k/2][64n] + 8 pad (72%32=8 -> conflict-free)
#define BR2 72    // gemm2 B [k/2][64n] x2 matrices

#define A_WORDS  (2 * BM * AR)
#define B1_WORDS (2 * 16 * BR1)
#define B2_WORDS (2 * 16 * BR2)

// ---------------- scratch ----------------
__device__ int      g_cnt[NE];
__device__ int      g_off[NE + 1];
__device__ int      g_tok[NP];
__device__ float    g_wt[NP];
__device__ unsigned g_hidh[(size_t)NT * NH / 2];   // fp16x2 hidden (8 MB)
__device__ unsigned g_acth[(size_t)NP * NI / 2];   // fp16x2 activations (11.5 MB)

// ---------------- fp16 helpers ----------------
__device__ __forceinline__ unsigned hpack(float lo, float hi) {
    __half2 h = __floats2half2_rn(lo, hi);
    return *(unsigned*)&h;
}
__device__ __forceinline__ uint4 hpack_rows(float4 r0, float4 r1) {
    uint4 w;
    w.x = hpack(r0.x, r1.x); w.y = hpack(r0.y, r1.y);
    w.z = hpack(r0.z, r1.z); w.w = hpack(r0.w, r1.w);
    return w;
}
__device__ __forceinline__ uint4 hpack_k(float4 a, float4 b) {
    uint4 w;
    w.x = hpack(a.x, a.y); w.y = hpack(a.z, a.w);
    w.z = hpack(b.x, b.y); w.w = hpack(b.z, b.w);
    return w;
}
__device__ __forceinline__ void mma16(float* c, const unsigned* a, const unsigned* b) {
    asm volatile(
        "mma.sync.aligned.m16n8k16.row.col.f32.f16.f16.f32 "
        "{%0,%1,%2,%3},{%4,%5,%6,%7},{%8,%9},{%0,%1,%2,%3};"
        : "+f"(c[0]), "+f"(c[1]), "+f"(c[2]), "+f"(c[3])
        : "r"(a[0]), "r"(a[1]), "r"(a[2]), "r"(a[3]), "r"(b[0]), "r"(b[1]));
}

// ---------------- fused init: prep (blocks 0..2047) + routing (block 2048) ----------------
__global__ __launch_bounds__(256) void k_init(
    const float* __restrict__ hidden, float* __restrict__ out,
    const int* __restrict__ idx, const float* __restrict__ w)
{
    if (blockIdx.x < (NT * NH / 8) / 256) {
        int i = blockIdx.x * 256 + threadIdx.x;
        float4 a = ((const float4*)hidden)[2 * i];
        float4 b = ((const float4*)hidden)[2 * i + 1];
        ((uint4*)g_hidh)[i] = hpack_k(a, b);
        ((float4*)out)[2 * i]     = make_float4(0.f, 0.f, 0.f, 0.f);
        ((float4*)out)[2 * i + 1] = make_float4(0.f, 0.f, 0.f, 0.f);
        return;
    }
    // routing block: 256 threads, 16 items each
    __shared__ int scnt[NE], soff[NE], sfill[NE];
    int tid = threadIdx.x;
    if (tid < NE) { scnt[tid] = 0; sfill[tid] = 0; }
    __syncthreads();
    int my_e[16];
#pragma unroll
    for (int j = 0; j < 16; j++) {
        int i = tid + j * 256;
        my_e[j] = idx[i];
        atomicAdd(&scnt[my_e[j]], 1);
    }
    __syncthreads();
    if (tid == 0) {
        int s = 0;
        for (int e = 0; e < NE; e++) {
            soff[e] = s; g_off[e] = s; g_cnt[e] = scnt[e]; s += scnt[e];
        }
        g_off[NE] = s;
    }
    __syncthreads();
#pragma unroll
    for (int j = 0; j < 16; j++) {
        int i = tid + j * 256;
        int e = my_e[j];
        int pos = soff[e] + atomicAdd(&sfill[e], 1);
        g_tok[pos] = i / TK;
        g_wt[pos]  = w[i];
    }
}

// ---------------- GEMM1: act = silu(X Wg) * (X Wu) ----------------
// CTA 128M x 64N x 2mat, 4 warps (2M x 2N), warp tile 64M x 32N x 2mat.  (R15 config)
__global__ __launch_bounds__(128, 2) void k_gemm1(
    const float* __restrict__ gate_w,
    const float* __restrict__ up_w)
{
    extern __shared__ unsigned sm[];
    unsigned* sA  = sm;
    unsigned* sBg = sA + A_WORDS;
    unsigned* sBu = sBg + B1_WORDS;
    int* toks = (int*)(sBu + B1_WORDS);

    int e = blockIdx.x % NE, cnt = g_cnt[e];
    int m0 = blockIdx.z * BM;
    if (m0 >= cnt) return;
    int base = g_off[e];
    int n0 = blockIdx.y * 64;
    int tid = threadIdx.x;

    if (tid < BM) {
        int m = m0 + tid;
        toks[tid] = (m < cnt) ? g_tok[base + m] : g_tok[base];
    }
    __syncthreads();

    const float* gp = gate_w + (size_t)e * NH * NI;
    const float* up = up_w   + (size_t)e * NH * NI;

    const unsigned* aSrc = g_hidh + (size_t)toks[tid] * (NH / 2);
    unsigned* aDst0 = sA + tid * AR;
    int k2a = tid >> 4,         n4a = (tid & 15) << 2;
    int k2b = (tid + 128) >> 4, n4b = ((tid + 128) & 15) << 2;
    const float* gA = gp + (size_t)(2 * k2a) * NI + n0 + n4a;
    const float* gB = gp + (size_t)(2 * k2b) * NI + n0 + n4b;
    const float* uA = up + (size_t)(2 * k2a) * NI + n0 + n4a;
    const float* uB = up + (size_t)(2 * k2b) * NI + n0 + n4b;
    unsigned bOffA = k2a * BR1 + n4a, bOffB = k2b * BR1 + n4b;

    {
        uint4 c0 = ((const uint4*)aSrc)[0], c1 = ((const uint4*)aSrc)[1];
        uint4 c2 = ((const uint4*)aSrc)[2], c3 = ((const uint4*)aSrc)[3];
        *(uint4*)(aDst0) = c0; *(uint4*)(aDst0 + 4) = c1;
        *(uint4*)(aDst0 + 8) = c2; *(uint4*)(aDst0 + 12) = c3;
        *(uint4*)(sBg + bOffA) = hpack_rows(*(const float4*)gA, *(const float4*)(gA + NI));
        *(uint4*)(sBg + bOffB) = hpack_rows(*(const float4*)gB, *(const float4*)(gB + NI));
        *(uint4*)(sBu + bOffA) = hpack_rows(*(const float4*)uA, *(const float4*)(uA + NI));
        *(uint4*)(sBu + bOffB) = hpack_rows(*(const float4*)uB, *(const float4*)(uB + NI));
    }
    __syncthreads();

    int lane = tid & 31, wid = tid >> 5;
    int wm = (wid & 1) * 64, wn = (wid >> 1) * 32;
    int grp = lane >> 2, tig = lane & 3;

    float accg[4][4][4] = {}, accu[4][4][4] = {};
    uint4 pa[4];
    float4 pg[4], pu[4];

    for (int k0 = 0; k0 < NH; k0 += BK) {
        int s = (k0 / BK) & 1;
        bool nxt = (k0 + BK) < NH;
        if (nxt) {
            int kn = k0 + BK;
            const unsigned* as = aSrc + (kn >> 1);
            pa[0] = ((const uint4*)as)[0]; pa[1] = ((const uint4*)as)[1];
            pa[2] = ((const uint4*)as)[2]; pa[3] = ((const uint4*)as)[3];
            pg[0] = *(const float4*)(gA + (size_t)kn * NI);
            pg[1] = *(const float4*)(gA + (size_t)(kn + 1) * NI);
            pg[2] = *(const float4*)(gB + (size_t)kn * NI);
            pg[3] = *(const float4*)(gB + (size_t)(kn + 1) * NI);
            pu[0] = *(const float4*)(uA + (size_t)kn * NI);
            pu[1] = *(const float4*)(uA + (size_t)(kn + 1) * NI);
            pu[2] = *(const float4*)(uB + (size_t)kn * NI);
            pu[3] = *(const float4*)(uB + (size_t)(kn + 1) * NI);
        }

        const unsigned* As = sA  + s * BM * AR;
        const unsigned* Bg = sBg + s * 16 * BR1;
        const unsigned* Bu = sBu + s * 16 * BR1;

#pragma unroll
        for (int kk = 0; kk < 2; kk++) {
            int k8 = kk * 8;
            unsigned a[4][4];
#pragma unroll
            for (int mi = 0; mi < 4; mi++) {
                int mb = wm + mi * 16 + grp;
                a[mi][0] = As[(mb    ) * AR + k8 + tig    ];
                a[mi][1] = As[(mb + 8) * AR + k8 + tig    ];
                a[mi][2] = As[(mb    ) * AR + k8 + tig + 4];
                a[mi][3] = As[(mb + 8) * AR + k8 + tig + 4];
            }
#pragma unroll
            for (int nj = 0; nj < 4; nj++) {
                int nb = wn + nj * 8 + grp;
                unsigned b[2];
                b[0] = Bg[(k8 + tig    ) * BR1 + nb];
                b[1] = Bg[(k8 + tig + 4) * BR1 + nb];
#pragma unroll
                for (int mi = 0; mi < 4; mi++) mma16(accg[mi][nj], a[mi], b);
                b[0] = Bu[(k8 + tig    ) * BR1 + nb];
                b[1] = Bu[(k8 + tig + 4) * BR1 + nb];
#pragma unroll
                for (int mi = 0; mi < 4; mi++) mma16(accu[mi][nj], a[mi], b);
            }
        }

        if (nxt) {
            int sn = s ^ 1;
            unsigned* An  = sA  + sn * BM * AR + tid * AR;
            unsigned* Bgn = sBg + sn * 16 * BR1;
            unsigned* Bun = sBu + sn * 16 * BR1;
            *(uint4*)(An) = pa[0]; *(uint4*)(An + 4) = pa[1];
            *(uint4*)(An + 8) = pa[2]; *(uint4*)(An + 12) = pa[3];
            *(uint4*)(Bgn + bOffA) = hpack_rows(pg[0], pg[1]);
            *(uint4*)(Bgn + bOffB) = hpack_rows(pg[2], pg[3]);
            *(uint4*)(Bun + bOffA) = hpack_rows(pu[0], pu[1]);
            *(uint4*)(Bun + bOffB) = hpack_rows(pu[2], pu[3]);
        }
        __syncthreads();
    }

#pragma unroll
    for (int mi = 0; mi < 4; mi++) {
#pragma unroll
        for (int nj = 0; nj < 4; nj++) {
            int mrow = wm + mi * 16 + grp;
            int ncol = n0 + wn + nj * 8 + tig * 2;
#pragma unroll
            for (int h = 0; h < 2; h++) {
                int mr = m0 + mrow + h * 8;
                if (mr < cnt) {
                    float g0 = accg[mi][nj][2*h],     u0 = accu[mi][nj][2*h];
                    float g1 = accg[mi][nj][2*h + 1], u1 = accu[mi][nj][2*h + 1];
                    float v0 = (g0 / (1.f + __expf(-g0))) * u0;
                    float v1 = (g1 / (1.f + __expf(-g1))) * u1;
                    g_acth[(size_t)(base + mr) * (NI / 2) + (ncol >> 1)] = hpack(v0, v1);
                }
            }
        }
    }
}

// ---------------- GEMM2: out[token] += wt * (act . Wd), dual-N ----------------
// R15 config: 256 threads, 8 warps (4M x 2N), warp 32x32 x dual-N matrices.
__global__ __launch_bounds__(256, 2) void k_gemm2(
    const float* __restrict__ down_w,
    float* __restrict__ out)
{
    extern __shared__ unsigned sm[];
    unsigned* sA  = sm;
    unsigned* sB0 = sA + A_WORDS;
    unsigned* sB1 = sB0 + B2_WORDS;
    int*   toks = (int*)(sB1 + B2_WORDS);
    float* wts  = (float*)(toks + BM);

    int e = blockIdx.z, cnt = g_cnt[e];
    int m0 = blockIdx.x * BM;
    if (m0 >= cnt) return;
    int base = g_off[e];
    int n0 = blockIdx.y * 128;
    int tid = threadIdx.x;

    if (tid < BM) {
        int m = m0 + tid;
        toks[tid] = (m < cnt) ? g_tok[base + m] : 0;
        wts[tid]  = (m < cnt) ? g_wt[base + m] : 0.f;
    }
    __syncthreads();

    const float* dp = down_w + (size_t)e * NI * NH;

    int a_m = tid >> 1, a_w = (tid & 1) << 3;
    int am = m0 + a_m;
    const unsigned* aSrc = g_acth + (size_t)(base + (am < cnt ? am : m0)) * (NI / 2) + a_w;
    unsigned* aDstBase = sA + a_m * AR + a_w;
    int b_k2 = tid >> 4, b_n4 = (tid & 15) << 2;
    const float* bSrc0 = dp + (size_t)(2 * b_k2) * NH + n0 + b_n4;
    const float* bSrc1 = bSrc0 + 64;
    unsigned bOff = b_k2 * BR2 + b_n4;

    {
        *(uint4*)(aDstBase)     = *(const uint4*)(aSrc);
        *(uint4*)(aDstBase + 4) = *(const uint4*)(aSrc + 4);
        float4 v00 = *(const float4*)(bSrc0);
        float4 v01 = *(const float4*)(bSrc0 + NH);
        float4 v10 = *(const float4*)(bSrc1);
        float4 v11 = *(const float4*)(bSrc1 + NH);
        *(uint4*)(sB0 + bOff) = hpack_rows(v00, v01);
        *(uint4*)(sB1 + bOff) = hpack_rows(v10, v11);
    }
    __syncthreads();

    int lane = tid & 31, wid = tid >> 5;
    int wm = (wid & 3) * 32, wn = (wid >> 2) * 32;
    int grp = lane >> 2, tig = lane & 3;

    float acc0[2][4][4] = {}, acc1[2][4][4] = {};
    uint4 pa[2];
    float4 pb0[2], pb1[2];

    for (int k0 = 0; k0 < NI; k0 += BK) {
        int s = (k0 / BK) & 1;
        bool nxt = (k0 + BK) < NI;
        if (nxt) {
            int kn = k0 + BK;
            pa[0] = *(const uint4*)(aSrc + (kn >> 1));
            pa[1] = *(const uint4*)(aSrc + (kn >> 1) + 4);
            pb0[0] = *(const float4*)(bSrc0 + (size_t)kn * NH);
            pb0[1] = *(const float4*)(bSrc0 + (size_t)(kn + 1) * NH);
            pb1[0] = *(const float4*)(bSrc1 + (size_t)kn * NH);
            pb1[1] = *(const float4*)(bSrc1 + (size_t)(kn + 1) * NH);
        }

        const unsigned* As = sA  + s * BM * AR;
        const unsigned* B0 = sB0 + s * 16 * BR2;
        const unsigned* B1 = sB1 + s * 16 * BR2;

#pragma unroll
        for (int kk = 0; kk < 2; kk++) {
            int k8 = kk * 8;
            unsigned a[2][4];
#pragma unroll
            for (int mi = 0; mi < 2; mi++) {
                int mb = wm + mi * 16 + grp;
                a[mi][0] = As[(mb    ) * AR + k8 + tig    ];
                a[mi][1] = As[(mb + 8) * AR + k8 + tig    ];
                a[mi][2] = As[(mb    ) * AR + k8 + tig + 4];
                a[mi][3] = As[(mb + 8) * AR + k8 + tig + 4];
            }
#pragma unroll
            for (int nj = 0; nj < 4; nj++) {
                int nb = wn + nj * 8 + grp;
                unsigned b[2];
                b[0] = B0[(k8 + tig    ) * BR2 + nb];
                b[1] = B0[(k8 + tig + 4) * BR2 + nb];
                mma16(acc0[0][nj], a[0], b);
                mma16(acc0[1][nj], a[1], b);
                b[0] = B1[(k8 + tig    ) * BR2 + nb];
                b[1] = B1[(k8 + tig + 4) * BR2 + nb];
                mma16(acc1[0][nj], a[0], b);
                mma16(acc1[1][nj], a[1], b);
            }
        }

        if (nxt) {
            int sn = s ^ 1;
            unsigned* An  = sA  + sn * BM * AR + a_m * AR + a_w;
            unsigned* Bn0 = sB0 + sn * 16 * BR2;
            unsigned* Bn1 = sB1 + sn * 16 * BR2;
            *(uint4*)(An)     = pa[0];
            *(uint4*)(An + 4) = pa[1];
            *(uint4*)(Bn0 + bOff) = hpack_rows(pb0[0], pb0[1]);
            *(uint4*)(Bn1 + bOff) = hpack_rows(pb1[0], pb1[1]);
        }
        __syncthreads();
    }

#pragma unroll
    for (int mi = 0; mi < 2; mi++) {
#pragma unroll
        for (int nj = 0; nj < 4; nj++) {
            int mloc = wm + mi * 16 + grp;
            int ncol = n0 + wn + nj * 8 + tig * 2;
#pragma unroll
            for (int h = 0; h < 2; h++) {
                int ml = mloc + h * 8;
                int mr = m0 + ml;
                if (mr < cnt) {
                    int   t = toks[ml];
                    float w = wts[ml];
                    float* dst = out + (size_t)t * NH + ncol;
                    asm volatile("red.global.add.v2.f32 [%0], {%1,%2};"
                                 :: "l"(dst), "f"(w * acc0[mi][nj][2*h]),
                                    "f"(w * acc0[mi][nj][2*h + 1]) : "memory");
                    asm volatile("red.global.add.v2.f32 [%0], {%1,%2};"
                                 :: "l"(dst + 64), "f"(w * acc1[mi][nj][2*h]),
                                    "f"(w * acc1[mi][nj][2*h + 1]) : "memory");
                }
            }
        }
    }
}

// ---------------- launch ----------------
extern "C" void kernel_launch(void* const* d_in, const int* in_sizes, int n_in,
                              void* d_out, int out_size)
{
    const float* hidden = (const float*)d_in[0];
    const int*   idx    = (const int*)  d_in[1];
    const float* topw   = (const float*)d_in[2];
    const float* gate_w = (const float*)d_in[3];
    const float* up_w   = (const float*)d_in[4];
    const float* down_w = (const float*)d_in[5];
    float* out = (float*)d_out;

    int smem1 = (A_WORDS + 2 * B1_WORDS) * 4 + BM * 4;
    int smem2 = (A_WORDS + 2 * B2_WORDS) * 4 + BM * 8;
    static int configured = 0;
    if (!configured) {
        cudaFuncSetAttribute(k_gemm1, cudaFuncAttributeMaxDynamicSharedMemorySize, smem1);
        cudaFuncSetAttribute(k_gemm2, cudaFuncAttributeMaxDynamicSharedMemorySize, smem2);
        configured = 1;
    }

    k_init<<<(NT * NH / 8) / 256 + 1, 256>>>(hidden, out, idx, topw);

    dim3 g1(NE, NI / 64, NP / BM);
    k_gemm1<<<g1, 128, smem1>>>(gate_w, up_w);

    dim3 g2(NP / BM, NH / 128, NE);
    k_gemm2<<<g2, 256, smem2>>>(down_w, out);
}